// round 5
// baseline (speedup 1.0000x reference)
#include <cuda_runtime.h>
#include <cuda_bf16.h>

#define HH 64
#define JCHUNK 16
#define WARPS_PER_BLOCK 4
#define THREADS (WARPS_PER_BLOCK * 32)
#define GRID_BLOCKS 2048

typedef unsigned long long u64;

// packed f32x2 fma: (d.lo, d.hi) = (a.lo*b.lo+c.lo, a.hi*b.hi+c.hi)
#define FMA2(d, a, b, c) \
    asm("fma.rn.f32x2 %0, %1, %2, %3;" : "=l"(d) : "l"(a), "l"(b), "l"(c))
#define PACK2(d, lo, hi) \
    asm("mov.b64 %0, {%1, %2};" : "=l"(d) : "f"(lo), "f"(hi))
#define UNPACK2(lo, hi, s) \
    asm("mov.b64 {%0, %1}, %2;" : "=f"(lo), "=f"(hi) : "l"(s))

// fast tanh + first three derivatives via ex2.approx + rcp.approx
// tanh(x) = 1 - 2/(1+exp(2x));  exp(2x) = 2^(2x*log2(e))
__device__ __forceinline__ void tanh_derivs(float x, float& f, float& f1, float& f2, float& f3) {
    float e, r;
    asm("ex2.approx.f32 %0, %1;" : "=f"(e) : "f"(x * 2.885390081777927f)); // 2*log2(e)
    asm("rcp.approx.f32 %0, %1;" : "=f"(r) : "f"(e + 1.0f));
    f  = fmaf(-2.0f, r, 1.0f);
    f1 = 1.0f - f * f;                 // f'
    f2 = -2.0f * f * f1;               // f''
    f3 = -2.0f * (f1 * f1 + f * f2);   // f'''
}

// Faa di Bruno: h = tanh(z(p,t)) jet composition, accumulate w3 * h-jet into acc.
// jet order: [0]=val [1]=p [2]=t [3]=pp [4]=pt [5]=tt [6]=ppp [7]=ppt [8]=ptt [9]=ttt
__device__ __forceinline__ void compose_acc(const float* z, float w3, float* acc) {
    float f, f1, f2, f3;
    tanh_derivs(z[0], f, f1, f2, f3);
    float zp = z[1], zt = z[2], zpp = z[3], zpt = z[4], ztt = z[5];
    float zppp = z[6], zppt = z[7], zptt = z[8], zttt = z[9];
    acc[1] = fmaf(w3, f1 * zp, acc[1]);
    acc[2] = fmaf(w3, f1 * zt, acc[2]);
    acc[3] = fmaf(w3, fmaf(f2, zp * zp, f1 * zpp), acc[3]);
    acc[4] = fmaf(w3, fmaf(f2, zp * zt, f1 * zpt), acc[4]);
    acc[5] = fmaf(w3, fmaf(f2, zt * zt, f1 * ztt), acc[5]);
    acc[6] = fmaf(w3, f3 * zp * zp * zp + 3.0f * f2 * zp * zpp + f1 * zppp, acc[6]);
    acc[7] = fmaf(w3, f3 * zp * zp * zt + f2 * (zpp * zt + 2.0f * zp * zpt) + f1 * zppt, acc[7]);
    acc[8] = fmaf(w3, f3 * zp * zt * zt + f2 * (ztt * zp + 2.0f * zt * zpt) + f1 * zptt, acc[8]);
    acc[9] = fmaf(w3, f3 * zt * zt * zt + 3.0f * f2 * zt * ztt + f1 * zttt, acc[9]);
}

__global__ __launch_bounds__(THREADS, 6) void pinn_flow_kernel(
    const float* __restrict__ phi, const float* __restrict__ theta,
    const float* __restrict__ radius, const float* __restrict__ hth,
    const float* __restrict__ hph, const float* __restrict__ brr,
    const float* __restrict__ W1, const float* __restrict__ b1,
    const float* __restrict__ W2, const float* __restrict__ b2,
    const float* __restrict__ W3, const float* __restrict__ b3,
    float* __restrict__ out, int n)
{
    // sW2d[j][hl] = (w[hl], w[hl], w[hl+16], w[hl+16])  — pre-duplicated u64 pairs
    __shared__ __align__(16) float4 sW2d[HH][16];                    // 16 KB
    // sW2e[j][hl] = (w[hl+32], w[hl+48])                 — packed at runtime
    __shared__ __align__(16) float2 sW2e[HH][16];                    // 8 KB
    __shared__ __align__(16) float  sL1[HH][12];                     // a,b,aa,ab,bb,aaa,aab,abb,bbb,b1
    __shared__ float sB2[HH];
    __shared__ float sW3[HH];
    // per-warp, per-j-in-chunk: point A jet (words 0-11), point B jet (words 12-23)
    __shared__ __align__(16) float sV[WARPS_PER_BLOCK][JCHUNK][24];  // 6 KB

    const int tid = threadIdx.x;
    for (int idx = tid; idx < HH * 16; idx += THREADS) {
        const int j  = idx >> 4;
        const int hl = idx & 15;
        const float w0 = W2[j * HH + hl];
        const float w1 = W2[j * HH + hl + 16];
        sW2d[j][hl] = make_float4(w0, w0, w1, w1);
        sW2e[j][hl] = make_float2(W2[j * HH + hl + 32], W2[j * HH + hl + 48]);
    }
    if (tid < HH) {
        sB2[tid] = b2[tid];
        sW3[tid] = W3[tid];
        float a = W1[tid];          // W1[0][j]  (coeff of phi)
        float b = W1[HH + tid];     // W1[1][j]  (coeff of theta)
        sL1[tid][0] = a;       sL1[tid][1] = b;
        sL1[tid][2] = a * a;   sL1[tid][3] = a * b;     sL1[tid][4] = b * b;
        sL1[tid][5] = a * a * a; sL1[tid][6] = a * a * b;
        sL1[tid][7] = a * b * b; sL1[tid][8] = b * b * b;
        sL1[tid][9] = b1[tid];
        sL1[tid][10] = 0.0f; sL1[tid][11] = 0.0f;
    }
    __syncthreads();

    const int lane = tid & 31;
    const int w    = tid >> 5;
    const int half = lane >> 4;          // 0 = point A, 1 = point B
    const int hl   = lane & 15;
    const int gw   = blockIdx.x * WARPS_PER_BLOCK + w;
    const int nwarps = gridDim.x * WARPS_PER_BLOCK;
    const int ntasks = (n + 1) >> 1;     // 2 points per warp-task

    for (int task = gw; task < ntasks; task += nwarps) {
        const int i = 2 * task + half;           // this half-warp's point
        const int iL = (i < n) ? i : (n - 1);    // clamped for loads
        const float p = phi[iL];
        const float t = theta[iL];

        u64 zp0[5], zp1[5], zp2[5], zp3[5];
        PACK2(zp0[0], sB2[hl],      0.0f);
        PACK2(zp1[0], sB2[hl + 16], 0.0f);
        PACK2(zp2[0], sB2[hl + 32], 0.0f);
        PACK2(zp3[0], sB2[hl + 48], 0.0f);
        #pragma unroll
        for (int c = 1; c < 5; ++c) { zp0[c] = 0ULL; zp1[c] = 0ULL; zp2[c] = 0ULL; zp3[c] = 0ULL; }

        #pragma unroll
        for (int chunk = 0; chunk < HH / JCHUNK; ++chunk) {
            // ---- Phase 1: layer-1 jet for unit j = 16*chunk + hl ----
            {
                const int j = JCHUNK * chunk + hl;
                const float4* lp = (const float4*)sL1[j];
                const float4 l0 = lp[0];                         // a, b, aa, ab
                const float4 l1 = lp[1];                         // bb, aaa, aab, abb
                const float2 l2 = *(const float2*)&sL1[j][8];    // bbb, b1
                const float z = fmaf(l0.x, p, fmaf(l0.y, t, l2.y));
                float f, f1, f2, f3;
                tanh_derivs(z, f, f1, f2, f3);
                float* vrow = &sV[w][hl][half * 12];
                *(float4*)&vrow[0] = make_float4(f, f1 * l0.x, f1 * l0.y, f2 * l0.z);
                *(float4*)&vrow[4] = make_float4(f2 * l0.w, f2 * l1.x, f3 * l1.y, f3 * l1.z);
                *(float2*)&vrow[8] = make_float2(f3 * l1.w, f3 * l2.x);
            }
            __syncwarp();

            // ---- Phase 2: accumulate z2 jets over this chunk's j ----
            const float* vbase = &sV[w][0][half * 12];
            #pragma unroll 2
            for (int jj = 0; jj < JCHUNK; ++jj) {
                const int j = JCHUNK * chunk + jj;
                const float* vrow = vbase + jj * 24;
                const ulonglong2 va = *(const ulonglong2*)&vrow[0];   // pairs 0,1
                const ulonglong2 vb = *(const ulonglong2*)&vrow[4];   // pairs 2,3
                const u64        vc = *(const u64*)&vrow[8];          // pair 4
                const ulonglong2 wdA = *(const ulonglong2*)&sW2d[j][hl]; // dup pairs u0,u1
                const float2 we = sW2e[j][hl];
                const u64 wd0 = wdA.x;
                const u64 wd1 = wdA.y;
                u64 wd2, wd3;
                PACK2(wd2, we.x, we.x);
                PACK2(wd3, we.y, we.y);
                FMA2(zp0[0], wd0, va.x, zp0[0]);  FMA2(zp1[0], wd1, va.x, zp1[0]);
                FMA2(zp2[0], wd2, va.x, zp2[0]);  FMA2(zp3[0], wd3, va.x, zp3[0]);
                FMA2(zp0[1], wd0, va.y, zp0[1]);  FMA2(zp1[1], wd1, va.y, zp1[1]);
                FMA2(zp2[1], wd2, va.y, zp2[1]);  FMA2(zp3[1], wd3, va.y, zp3[1]);
                FMA2(zp0[2], wd0, vb.x, zp0[2]);  FMA2(zp1[2], wd1, vb.x, zp1[2]);
                FMA2(zp2[2], wd2, vb.x, zp2[2]);  FMA2(zp3[2], wd3, vb.x, zp3[2]);
                FMA2(zp0[3], wd0, vb.y, zp0[3]);  FMA2(zp1[3], wd1, vb.y, zp1[3]);
                FMA2(zp2[3], wd2, vb.y, zp2[3]);  FMA2(zp3[3], wd3, vb.y, zp3[3]);
                FMA2(zp0[4], wd0, vc,   zp0[4]);  FMA2(zp1[4], wd1, vc,   zp1[4]);
                FMA2(zp2[4], wd2, vc,   zp2[4]);  FMA2(zp3[4], wd3, vc,   zp3[4]);
            }
            __syncwarp();   // chunk's sV consumed; safe to overwrite
        }

        // ---- Phase 3: unpack, tanh-compose, weight by W3, reduce over half-warp ----
        float acc[10];
        #pragma unroll
        for (int cc = 0; cc < 10; ++cc) acc[cc] = 0.0f;
        {
            float z[10];
            #pragma unroll
            for (int c = 0; c < 5; ++c) UNPACK2(z[2 * c], z[2 * c + 1], zp0[c]);
            compose_acc(z, sW3[hl], acc);
            #pragma unroll
            for (int c = 0; c < 5; ++c) UNPACK2(z[2 * c], z[2 * c + 1], zp1[c]);
            compose_acc(z, sW3[hl + 16], acc);
            #pragma unroll
            for (int c = 0; c < 5; ++c) UNPACK2(z[2 * c], z[2 * c + 1], zp2[c]);
            compose_acc(z, sW3[hl + 32], acc);
            #pragma unroll
            for (int c = 0; c < 5; ++c) UNPACK2(z[2 * c], z[2 * c + 1], zp3[c]);
            compose_acc(z, sW3[hl + 48], acc);
        }

        #pragma unroll
        for (int cc = 1; cc < 10; ++cc) {
            float v = acc[cc];
            #pragma unroll
            for (int off = 8; off; off >>= 1)
                v += __shfl_xor_sync(0xffffffffu, v, off);
            acc[cc] = v;
        }

        if (hl == 0 && i < n) {
            const float Tp = acc[1], Tt = acc[2];
            const float Tpp = acc[3], Tpt = acc[4], Ttt = acc[5];
            const float Tppp = acc[6], Tppt = acc[7], Tptt = acc[8], Tttt = acc[9];

            float s, cn;
            sincosf(t, &s, &cn);
            const float r    = radius[i];
            const float invs = 1.0f / s;
            const float invr = 1.0f / r;

            const float ut = fmaf(Tp, invs, Tt);
            const float up = fmaf(Tp, invs, -Tt);

            const float u_th_t = -(Tpt + cn * Tt + s * Ttt);
            const float u_ph_p = fmaf(Tpp, invs, -Tpt);
            const float div = (u_th_t + u_ph_p) * invs * invr;

            const float c2s2 = cn * cn - s * s;
            const float u_th_tt = -(cn * Tpt + s * Tptt + 3.0f * s * cn * Ttt
                                    + c2s2 * Tt + s * s * Tttt);
            const float u_th_pp = -(fmaf(Tppp, invs, Tppt));
            const float u_ph_tt = cn * Tpt + s * Tptt - c2s2 * Tt
                                  - 3.0f * s * cn * Ttt - s * s * Tttt;
            const float u_ph_pp = fmaf(Tppp, invs, -Tppt);

            const float invr2  = invr * invr;
            const float invrs2 = invs * invs * invr2;
            const float lapt = fmaf(s * invr2, u_th_tt, u_th_pp * invrs2);
            const float lapp = fmaf(s * invr2, u_ph_tt, u_ph_pp * invrs2);
            const float comp = s * (lapt * lapt + lapp * lapp);
            const float sv   = -(ut * hth[i] + up * hph[i]) - brr[i] * div;
            const float tg   = div - ut * (s / cn) * invr;

            out[i]         = ut;
            out[n + i]     = up;
            out[2 * n + i] = div;
            out[3 * n + i] = sv;
            out[4 * n + i] = tg;
            out[5 * n + i] = comp;
        }
    }
}

extern "C" void kernel_launch(void* const* d_in, const int* in_sizes, int n_in,
                              void* d_out, int out_size) {
    const float* phi    = (const float*)d_in[0];
    const float* theta  = (const float*)d_in[1];
    const float* radius = (const float*)d_in[2];
    const float* hth    = (const float*)d_in[3];
    const float* hph    = (const float*)d_in[4];
    const float* brr    = (const float*)d_in[5];
    const float* W1     = (const float*)d_in[6];
    const float* b1     = (const float*)d_in[7];
    const float* W2     = (const float*)d_in[8];
    const float* b2     = (const float*)d_in[9];
    const float* W3     = (const float*)d_in[10];
    const float* b3     = (const float*)d_in[11];
    float* out = (float*)d_out;
    const int n = in_sizes[0];

    pinn_flow_kernel<<<GRID_BLOCKS, THREADS>>>(
        phi, theta, radius, hth, hph, brr,
        W1, b1, W2, b2, W3, b3, out, n);
}

// round 6
// speedup vs baseline: 1.0332x; 1.0332x over previous
#include <cuda_runtime.h>
#include <cuda_bf16.h>

#define HH 64
#define JCHUNK 32
#define WARPS_PER_BLOCK 4
#define THREADS 128
#define GRID_BLOCKS 888

typedef unsigned long long u64;

// packed f32x2 ops
#define FMA2(d, a, b, c) \
    asm("fma.rn.f32x2 %0, %1, %2, %3;" : "=l"(d) : "l"(a), "l"(b), "l"(c))
#define MUL2(d, a, b) \
    asm("mul.rn.f32x2 %0, %1, %2;" : "=l"(d) : "l"(a), "l"(b))
#define ADD2(d, a, b) \
    asm("add.rn.f32x2 %0, %1, %2;" : "=l"(d) : "l"(a), "l"(b))
#define PACK2(d, lo, hi) \
    asm("mov.b64 %0, {%1, %2};" : "=l"(d) : "f"(lo), "f"(hi))
#define UNPACK2(lo, hi, s) \
    asm("mov.b64 {%0, %1}, %2;" : "=f"(lo), "=f"(hi) : "l"(s))

// fast tanh + first three derivatives via ex2.approx + rcp.approx
__device__ __forceinline__ void tanh_derivs(float x, float& f, float& f1, float& f2, float& f3) {
    float e, r;
    asm("ex2.approx.f32 %0, %1;" : "=f"(e) : "f"(x * 2.885390081777927f)); // 2*log2(e)
    asm("rcp.approx.f32 %0, %1;" : "=f"(r) : "f"(e + 1.0f));
    f  = fmaf(-2.0f, r, 1.0f);
    f1 = 1.0f - f * f;
    f2 = -2.0f * f * f1;
    f3 = -2.0f * (f1 * f1 + f * f2);
}

// Faa di Bruno jet composition on point-pairs (all values are (ptA,ptB) f32x2).
// z jet order: [0]=val [1]=p [2]=t [3]=pp [4]=pt [5]=tt [6]=ppp [7]=ppt [8]=ptt [9]=ttt
__device__ __forceinline__ void compose_pair(const u64* z, u64 w3d, u64* acc, u64 THREEd) {
    float za, zb;
    UNPACK2(za, zb, z[0]);
    float fa, f1a, f2a, f3a, fb, f1b, f2b, f3b;
    tanh_derivs(za, fa, f1a, f2a, f3a);
    tanh_derivs(zb, fb, f1b, f2b, f3b);
    u64 F1, F2, F3;
    PACK2(F1, f1a, f1b);
    PACK2(F2, f2a, f2b);
    PACK2(F3, f3a, f3b);
    const u64 Zp = z[1], Zt = z[2], Zpp = z[3], Zpt = z[4], Ztt = z[5];
    const u64 Zppp = z[6], Zppt = z[7], Zptt = z[8], Zttt = z[9];
    u64 t, u, v;
    u64 Zp2, Zt2, ZpZt;
    MUL2(Zp2, Zp, Zp);
    MUL2(Zt2, Zt, Zt);
    MUL2(ZpZt, Zp, Zt);
    // acc1 += w3 * f1*Zp
    MUL2(t, F1, Zp);            FMA2(acc[1], w3d, t, acc[1]);
    MUL2(t, F1, Zt);            FMA2(acc[2], w3d, t, acc[2]);
    // acc3 += w3 * (f2*Zp^2 + f1*Zpp)
    MUL2(u, F1, Zpp);           FMA2(t, F2, Zp2, u);            FMA2(acc[3], w3d, t, acc[3]);
    MUL2(u, F1, Zpt);           FMA2(t, F2, ZpZt, u);           FMA2(acc[4], w3d, t, acc[4]);
    MUL2(u, F1, Ztt);           FMA2(t, F2, Zt2, u);            FMA2(acc[5], w3d, t, acc[5]);
    // acc6 += w3 * (f3*Zp^3 + 3 f2 Zp Zpp + f1 Zppp)
    MUL2(u, Zp, Zpp);  MUL2(u, u, THREEd);
    MUL2(v, F1, Zppp); FMA2(v, F2, u, v);
    MUL2(t, Zp2, Zp);  FMA2(t, F3, t, v);                       FMA2(acc[6], w3d, t, acc[6]);
    // acc7 += w3 * (f3 Zp^2 Zt + f2 (Zpp Zt + 2 Zp Zpt) + f1 Zppt)
    MUL2(u, Zp, Zpt);  ADD2(u, u, u);  FMA2(u, Zpp, Zt, u);
    MUL2(v, F1, Zppt); FMA2(v, F2, u, v);
    MUL2(t, Zp2, Zt);  FMA2(t, F3, t, v);                       FMA2(acc[7], w3d, t, acc[7]);
    // acc8 += w3 * (f3 Zp Zt^2 + f2 (Ztt Zp + 2 Zt Zpt) + f1 Zptt)
    MUL2(u, Zt, Zpt);  ADD2(u, u, u);  FMA2(u, Ztt, Zp, u);
    MUL2(v, F1, Zptt); FMA2(v, F2, u, v);
    MUL2(t, Zt2, Zp);  FMA2(t, F3, t, v);                       FMA2(acc[8], w3d, t, acc[8]);
    // acc9 += w3 * (f3 Zt^3 + 3 f2 Zt Ztt + f1 Zttt)
    MUL2(u, Zt, Ztt);  MUL2(u, u, THREEd);
    MUL2(v, F1, Zttt); FMA2(v, F2, u, v);
    MUL2(t, Zt2, Zt);  FMA2(t, F3, t, v);                       FMA2(acc[9], w3d, t, acc[9]);
}

__global__ __launch_bounds__(THREADS, 6) void pinn_flow_kernel(
    const float* __restrict__ phi, const float* __restrict__ theta,
    const float* __restrict__ radius, const float* __restrict__ hth,
    const float* __restrict__ hph, const float* __restrict__ brr,
    const float* __restrict__ W1, const float* __restrict__ b1,
    const float* __restrict__ W2, const float* __restrict__ b2,
    const float* __restrict__ W3, const float* __restrict__ b3,
    float* __restrict__ out, int n)
{
    // sW2p[j][lane] = (W2[j][lane], W2[j][lane+32])
    __shared__ __align__(16) float2 sW2p[HH][32];                 // 16 KB
    // duplicated layer-1 monomials per unit: a,b,aa,ab,bb,aaa,aab,abb,bbb,b1 (pad 12)
    __shared__ __align__(16) u64 sL1d[HH][12];                    // 6 KB
    __shared__ u64 sB2d[HH];                                      // 512 B
    __shared__ u64 sW3d[HH];                                      // 512 B
    // per-warp jet pairs for current chunk: row j -> 10 u64 (80 B)
    __shared__ __align__(16) u64 sV[WARPS_PER_BLOCK][JCHUNK][10]; // 10 KB

    const int tid = threadIdx.x;
    for (int idx = tid; idx < HH * 32; idx += THREADS) {
        const int j = idx >> 5;
        const int k = idx & 31;
        sW2p[j][k] = make_float2(W2[j * HH + k], W2[j * HH + k + 32]);
    }
    if (tid < HH) {
        u64 d;
        PACK2(d, b2[tid], b2[tid]); sB2d[tid] = d;
        PACK2(d, W3[tid], W3[tid]); sW3d[tid] = d;
        const float a = W1[tid];        // W1[0][j]
        const float b = W1[HH + tid];   // W1[1][j]
        float m[10] = {a, b, a*a, a*b, b*b, a*a*a, a*a*b, a*b*b, b*b*b, b1[tid]};
        #pragma unroll
        for (int c = 0; c < 10; ++c) { PACK2(d, m[c], m[c]); sL1d[tid][c] = d; }
        sL1d[tid][10] = 0ULL; sL1d[tid][11] = 0ULL;
    }
    __syncthreads();

    const int lane = tid & 31;
    const int w    = tid >> 5;
    const int gw   = blockIdx.x * WARPS_PER_BLOCK + w;
    const int nwarps = GRID_BLOCKS * WARPS_PER_BLOCK;
    const int ntasks = (n + 1) >> 1;     // 2 points per warp-task

    u64 THREEd, ONEd, M2d;
    PACK2(THREEd, 3.0f, 3.0f);
    PACK2(ONEd, 1.0f, 1.0f);
    PACK2(M2d, -2.0f, -2.0f);
    (void)ONEd; (void)M2d;

    for (int task = gw; task < ntasks; task += nwarps) {
        const int iA = 2 * task;
        const int iB = (2 * task + 1 < n) ? 2 * task + 1 : n - 1;
        u64 ppair, tpair;
        PACK2(ppair, phi[iA], phi[iB]);
        PACK2(tpair, theta[iA], theta[iB]);

        // accumulators: zA = unit lane, zB = unit lane+32; each coeff is a point-pair
        u64 zA[10], zB[10];
        zA[0] = sB2d[lane];
        zB[0] = sB2d[lane + 32];
        #pragma unroll
        for (int c = 1; c < 10; ++c) { zA[c] = 0ULL; zB[c] = 0ULL; }

        #pragma unroll
        for (int chunk = 0; chunk < HH / JCHUNK; ++chunk) {
            // ---- Phase 1: jet pair for unit j = 32*chunk + lane ----
            {
                const int j = JCHUNK * chunk + lane;
                const ulonglong2* lr = (const ulonglong2*)sL1d[j];
                const ulonglong2 m01 = lr[0];   // a_d, b_d
                const ulonglong2 m23 = lr[1];   // aa_d, ab_d
                const ulonglong2 m45 = lr[2];   // bb_d, aaa_d
                const ulonglong2 m67 = lr[3];   // aab_d, abb_d
                const ulonglong2 m89 = lr[4];   // bbb_d, b1_d
                u64 zpr;
                FMA2(zpr, m01.y, tpair, m89.y);
                FMA2(zpr, m01.x, ppair, zpr);
                float za, zb;
                UNPACK2(za, zb, zpr);
                float fa, f1a, f2a, f3a, fb, f1b, f2b, f3b;
                tanh_derivs(za, fa, f1a, f2a, f3a);
                tanh_derivs(zb, fb, f1b, f2b, f3b);
                u64 F, F1, F2, F3;
                PACK2(F,  fa,  fb);
                PACK2(F1, f1a, f1b);
                PACK2(F2, f2a, f2b);
                PACK2(F3, f3a, f3b);
                u64 V1, V2, V3, V4, V5, V6, V7, V8, V9;
                MUL2(V1, m01.x, F1);
                MUL2(V2, m01.y, F1);
                MUL2(V3, m23.x, F2);
                MUL2(V4, m23.y, F2);
                MUL2(V5, m45.x, F2);
                MUL2(V6, m45.y, F3);
                MUL2(V7, m67.x, F3);
                MUL2(V8, m67.y, F3);
                MUL2(V9, m89.x, F3);
                ulonglong2* vr = (ulonglong2*)sV[w][lane];
                vr[0] = make_ulonglong2(F,  V1);
                vr[1] = make_ulonglong2(V2, V3);
                vr[2] = make_ulonglong2(V4, V5);
                vr[3] = make_ulonglong2(V6, V7);
                vr[4] = make_ulonglong2(V8, V9);
            }
            __syncwarp();

            // ---- Phase 2: accumulate z2 jet pairs over this chunk's j ----
            #pragma unroll 16
            for (int jj = 0; jj < JCHUNK; ++jj) {
                const ulonglong2* vr = (const ulonglong2*)sV[w][jj];
                const ulonglong2 v01 = vr[0];
                const ulonglong2 v23 = vr[1];
                const ulonglong2 v45 = vr[2];
                const ulonglong2 v67 = vr[3];
                const ulonglong2 v89 = vr[4];
                const float2 wv = sW2p[JCHUNK * chunk + jj][lane];
                u64 w0d, w1d;
                PACK2(w0d, wv.x, wv.x);
                PACK2(w1d, wv.y, wv.y);
                FMA2(zA[0], w0d, v01.x, zA[0]);  FMA2(zB[0], w1d, v01.x, zB[0]);
                FMA2(zA[1], w0d, v01.y, zA[1]);  FMA2(zB[1], w1d, v01.y, zB[1]);
                FMA2(zA[2], w0d, v23.x, zA[2]);  FMA2(zB[2], w1d, v23.x, zB[2]);
                FMA2(zA[3], w0d, v23.y, zA[3]);  FMA2(zB[3], w1d, v23.y, zB[3]);
                FMA2(zA[4], w0d, v45.x, zA[4]);  FMA2(zB[4], w1d, v45.x, zB[4]);
                FMA2(zA[5], w0d, v45.y, zA[5]);  FMA2(zB[5], w1d, v45.y, zB[5]);
                FMA2(zA[6], w0d, v67.x, zA[6]);  FMA2(zB[6], w1d, v67.x, zB[6]);
                FMA2(zA[7], w0d, v67.y, zA[7]);  FMA2(zB[7], w1d, v67.y, zB[7]);
                FMA2(zA[8], w0d, v89.x, zA[8]);  FMA2(zB[8], w1d, v89.x, zB[8]);
                FMA2(zA[9], w0d, v89.y, zA[9]);  FMA2(zB[9], w1d, v89.y, zB[9]);
            }
            __syncwarp();   // chunk's sV consumed; safe to overwrite next chunk
        }

        // ---- Phase 3: compose both units, reduce pairs over the warp ----
        u64 acc[10];
        #pragma unroll
        for (int c = 0; c < 10; ++c) acc[c] = 0ULL;
        compose_pair(zA, sW3d[lane],      acc, THREEd);
        compose_pair(zB, sW3d[lane + 32], acc, THREEd);

        #pragma unroll
        for (int c = 1; c < 10; ++c) {
            u64 v = acc[c];
            #pragma unroll
            for (int off = 16; off; off >>= 1) {
                u64 o = __shfl_xor_sync(0xffffffffu, v, off);
                ADD2(v, v, o);
            }
            acc[c] = v;
        }

        if (lane < 2) {
            const int i = 2 * task + lane;
            if (i < n) {
                float T[10];
                #pragma unroll
                for (int c = 1; c < 10; ++c) {
                    float lo, hi;
                    UNPACK2(lo, hi, acc[c]);
                    T[c] = (lane == 0) ? lo : hi;
                }
                const float Tp = T[1], Tt = T[2];
                const float Tpp = T[3], Tpt = T[4], Ttt = T[5];
                const float Tppp = T[6], Tppt = T[7], Tptt = T[8], Tttt = T[9];

                const float t = theta[i];
                float s, cn;
                sincosf(t, &s, &cn);
                const float r    = radius[i];
                const float invs = 1.0f / s;
                const float invr = 1.0f / r;

                const float ut = fmaf(Tp, invs, Tt);
                const float up = fmaf(Tp, invs, -Tt);

                const float u_th_t = -(Tpt + cn * Tt + s * Ttt);
                const float u_ph_p = fmaf(Tpp, invs, -Tpt);
                const float div = (u_th_t + u_ph_p) * invs * invr;

                const float c2s2 = cn * cn - s * s;
                const float u_th_tt = -(cn * Tpt + s * Tptt + 3.0f * s * cn * Ttt
                                        + c2s2 * Tt + s * s * Tttt);
                const float u_th_pp = -(fmaf(Tppp, invs, Tppt));
                const float u_ph_tt = cn * Tpt + s * Tptt - c2s2 * Tt
                                      - 3.0f * s * cn * Ttt - s * s * Tttt;
                const float u_ph_pp = fmaf(Tppp, invs, -Tppt);

                const float invr2  = invr * invr;
                const float invrs2 = invs * invs * invr2;
                const float lapt = fmaf(s * invr2, u_th_tt, u_th_pp * invrs2);
                const float lapp = fmaf(s * invr2, u_ph_tt, u_ph_pp * invrs2);
                const float comp = s * (lapt * lapt + lapp * lapp);
                const float sv   = -(ut * hth[i] + up * hph[i]) - brr[i] * div;
                const float tg   = div - ut * (s / cn) * invr;

                out[i]         = ut;
                out[n + i]     = up;
                out[2 * n + i] = div;
                out[3 * n + i] = sv;
                out[4 * n + i] = tg;
                out[5 * n + i] = comp;
            }
        }
    }
}

extern "C" void kernel_launch(void* const* d_in, const int* in_sizes, int n_in,
                              void* d_out, int out_size) {
    const float* phi    = (const float*)d_in[0];
    const float* theta  = (const float*)d_in[1];
    const float* radius = (const float*)d_in[2];
    const float* hth    = (const float*)d_in[3];
    const float* hph    = (const float*)d_in[4];
    const float* brr    = (const float*)d_in[5];
    const float* W1     = (const float*)d_in[6];
    const float* b1     = (const float*)d_in[7];
    const float* W2     = (const float*)d_in[8];
    const float* b2     = (const float*)d_in[9];
    const float* W3     = (const float*)d_in[10];
    const float* b3     = (const float*)d_in[11];
    float* out = (float*)d_out;
    const int n = in_sizes[0];

    pinn_flow_kernel<<<GRID_BLOCKS, THREADS>>>(
        phi, theta, radius, hth, hph, brr,
        W1, b1, W2, b2, W3, b3, out, n);
}

// round 7
// speedup vs baseline: 1.4347x; 1.3885x over previous
#include <cuda_runtime.h>
#include <cuda_bf16.h>

#define HH 64
#define GRID_BLOCKS 2048
#define THREADS 128

// fast tanh + first three derivatives via ex2.approx + rcp.approx
__device__ __forceinline__ void tanh_derivs(float x, float& f, float& f1, float& f2, float& f3) {
    float e, r;
    asm("ex2.approx.f32 %0, %1;" : "=f"(e) : "f"(x * 2.885390081777927f)); // 2*log2(e)
    asm("rcp.approx.f32 %0, %1;" : "=f"(r) : "f"(e + 1.0f));
    f  = fmaf(-2.0f, r, 1.0f);
    f1 = 1.0f - f * f;
    f2 = -2.0f * f * f1;
    f3 = -2.0f * (f1 * f1 + f * f2);
}

// split f32 into tf32-exact hi (top 10 mantissa bits) + residual lo
__device__ __forceinline__ void tf32_split(float v, unsigned& hi, unsigned& lo) {
    unsigned h = __float_as_uint(v) & 0xFFFFE000u;
    hi = h;
    lo = __float_as_uint(v - __uint_as_float(h));
}

// mma.m16n8k8 tf32: C[4] += A(uint4) * B(b0,b1)
#define MMA_TF32(C, A, b0, b1) \
    asm("mma.sync.aligned.m16n8k8.row.col.f32.tf32.tf32.f32 " \
        "{%0,%1,%2,%3},{%4,%5,%6,%7},{%8,%9},{%0,%1,%2,%3};" \
        : "+f"((C)[0]), "+f"((C)[1]), "+f"((C)[2]), "+f"((C)[3]) \
        : "r"((A).x), "r"((A).y), "r"((A).z), "r"((A).w), "r"(b0), "r"(b1))

// Faa di Bruno: accumulate w3 * jet(tanh(z)) into acc9[0..8] (coeffs p,t,pp,pt,tt,ppp,ppt,ptt,ttt)
__device__ __forceinline__ void compose_scalar(const float* z, float w3, float* acc9) {
    float f, f1, f2, f3;
    tanh_derivs(z[0], f, f1, f2, f3);
    const float zp = z[1], zt = z[2], zpp = z[3], zpt = z[4], ztt = z[5];
    const float zppp = z[6], zppt = z[7], zptt = z[8], zttt = z[9];
    acc9[0] = fmaf(w3, f1 * zp, acc9[0]);
    acc9[1] = fmaf(w3, f1 * zt, acc9[1]);
    acc9[2] = fmaf(w3, fmaf(f2, zp * zp, f1 * zpp), acc9[2]);
    acc9[3] = fmaf(w3, fmaf(f2, zp * zt, f1 * zpt), acc9[3]);
    acc9[4] = fmaf(w3, fmaf(f2, zt * zt, f1 * ztt), acc9[4]);
    acc9[5] = fmaf(w3, f3 * zp * zp * zp + 3.0f * f2 * zp * zpp + f1 * zppp, acc9[5]);
    acc9[6] = fmaf(w3, f3 * zp * zp * zt + f2 * (zpp * zt + 2.0f * zp * zpt) + f1 * zppt, acc9[6]);
    acc9[7] = fmaf(w3, f3 * zp * zt * zt + f2 * (ztt * zp + 2.0f * zt * zpt) + f1 * zptt, acc9[7]);
    acc9[8] = fmaf(w3, f3 * zt * zt * zt + 3.0f * f2 * zt * ztt + f1 * zttt, acc9[8]);
}

__global__ __launch_bounds__(THREADS, 4) void pinn_flow_kernel(
    const float* __restrict__ phi, const float* __restrict__ theta,
    const float* __restrict__ radius, const float* __restrict__ hth,
    const float* __restrict__ hph, const float* __restrict__ brr,
    const float* __restrict__ W1, const float* __restrict__ b1,
    const float* __restrict__ W2, const float* __restrict__ b2,
    const float* __restrict__ W3, const float* __restrict__ b3,
    float* __restrict__ out, int n)
{
    // A-operand tables: W2^T arranged per-lane for m16n8k8 A-fragments.
    // Index [kq][chunk][lane]: a0=W2[j0][kb+gid], a1=W2[j0][kb+gid+8],
    //                          a2=W2[j1][kb+gid], a3=W2[j1][kb+gid+8]
    // where gid=lane>>2, tig=lane&3, j0=chunk*8+tig, j1=j0+4, kb=kq*16.
    __shared__ __align__(16) uint4 sAhi[4][8][32];   // 16 KB
    __shared__ __align__(16) uint4 sAlo[4][8][32];   // 16 KB
    __shared__ __align__(16) float sL1[HH][12];      // a,b,aa,ab,bb,aaa,aab,abb,bbb,b1 (pad 12)
    __shared__ float sB2[HH];
    __shared__ float sW3[HH];

    const int tid = threadIdx.x;

    // build A tables (hi/lo split of W2^T)
    for (int idx = tid; idx < 4 * 8 * 32; idx += THREADS) {
        const int kq    = idx >> 8;
        const int chunk = (idx >> 5) & 7;
        const int ln    = idx & 31;
        const int gid = ln >> 2, tig = ln & 3;
        const int j0 = chunk * 8 + tig;
        const int j1 = j0 + 4;
        const int kb = kq * 16;
        const float a0 = W2[j0 * HH + kb + gid];
        const float a1 = W2[j0 * HH + kb + gid + 8];
        const float a2 = W2[j1 * HH + kb + gid];
        const float a3 = W2[j1 * HH + kb + gid + 8];
        unsigned h0, l0, h1, l1, h2, l2, h3, l3;
        tf32_split(a0, h0, l0);
        tf32_split(a1, h1, l1);
        tf32_split(a2, h2, l2);
        tf32_split(a3, h3, l3);
        sAhi[kq][chunk][ln] = make_uint4(h0, h1, h2, h3);
        sAlo[kq][chunk][ln] = make_uint4(l0, l1, l2, l3);
    }
    if (tid < HH) {
        sB2[tid] = b2[tid];
        sW3[tid] = W3[tid];
        const float a = W1[tid];        // W1[0][j]
        const float b = W1[HH + tid];   // W1[1][j]
        sL1[tid][0] = a;       sL1[tid][1] = b;
        sL1[tid][2] = a * a;   sL1[tid][3] = a * b;     sL1[tid][4] = b * b;
        sL1[tid][5] = a * a * a; sL1[tid][6] = a * a * b;
        sL1[tid][7] = a * b * b; sL1[tid][8] = b * b * b;
        sL1[tid][9] = b1[tid];
        sL1[tid][10] = 0.0f; sL1[tid][11] = 0.0f;
    }
    __syncthreads();

    const int lane = tid & 31;
    const int w    = tid >> 5;
    const int gid  = lane >> 2;   // 0..7
    const int tig  = lane & 3;    // 0..3
    const int ntiles = (n + 31) >> 5;   // 32 points per block-tile (8 per warp)

    for (int tile = blockIdx.x; tile < ntiles; tile += gridDim.x) {
        const int base = tile * 32 + w * 8;     // this warp's 8 points
        const int myp  = base + gid;            // point for B-fragment building
        const int mypL = (myp < n) ? myp : (n - 1);
        const float p = phi[mypL];
        const float t = theta[mypL];

        // T-jet partials: [col 0: coeffs 1..9][col 1: coeffs 1..9]
        float Tj[18];
        #pragma unroll
        for (int q = 0; q < 18; ++q) Tj[q] = 0.0f;

        #pragma unroll 1
        for (int kq = 0; kq < 4; ++kq) {
            float C[10][4];
            #pragma unroll
            for (int c = 0; c < 10; ++c) {
                C[c][0] = 0.0f; C[c][1] = 0.0f; C[c][2] = 0.0f; C[c][3] = 0.0f;
            }

            #pragma unroll 1
            for (int chunk = 0; chunk < 8; ++chunk) {
                // ---- phase 1: tanh jets for (j0, myp) and (j1, myp), directly as B-frags ----
                unsigned Bhi0[10], Blo0[10], Bhi1[10], Blo1[10];
                {
                    const int j0 = chunk * 8 + tig;
                    const float4 m0 = *(const float4*)&sL1[j0][0];   // a,b,aa,ab
                    const float4 m1 = *(const float4*)&sL1[j0][4];   // bb,aaa,aab,abb
                    const float2 m2 = *(const float2*)&sL1[j0][8];   // bbb,b1
                    const float z1 = fmaf(m0.x, p, fmaf(m0.y, t, m2.y));
                    float f, f1, f2, f3;
                    tanh_derivs(z1, f, f1, f2, f3);
                    tf32_split(f,        Bhi0[0], Blo0[0]);
                    tf32_split(f1 * m0.x, Bhi0[1], Blo0[1]);
                    tf32_split(f1 * m0.y, Bhi0[2], Blo0[2]);
                    tf32_split(f2 * m0.z, Bhi0[3], Blo0[3]);
                    tf32_split(f2 * m0.w, Bhi0[4], Blo0[4]);
                    tf32_split(f2 * m1.x, Bhi0[5], Blo0[5]);
                    tf32_split(f3 * m1.y, Bhi0[6], Blo0[6]);
                    tf32_split(f3 * m1.z, Bhi0[7], Blo0[7]);
                    tf32_split(f3 * m1.w, Bhi0[8], Blo0[8]);
                    tf32_split(f3 * m2.x, Bhi0[9], Blo0[9]);
                }
                {
                    const int j1 = chunk * 8 + tig + 4;
                    const float4 m0 = *(const float4*)&sL1[j1][0];
                    const float4 m1 = *(const float4*)&sL1[j1][4];
                    const float2 m2 = *(const float2*)&sL1[j1][8];
                    const float z1 = fmaf(m0.x, p, fmaf(m0.y, t, m2.y));
                    float f, f1, f2, f3;
                    tanh_derivs(z1, f, f1, f2, f3);
                    tf32_split(f,        Bhi1[0], Blo1[0]);
                    tf32_split(f1 * m0.x, Bhi1[1], Blo1[1]);
                    tf32_split(f1 * m0.y, Bhi1[2], Blo1[2]);
                    tf32_split(f2 * m0.z, Bhi1[3], Blo1[3]);
                    tf32_split(f2 * m0.w, Bhi1[4], Blo1[4]);
                    tf32_split(f2 * m1.x, Bhi1[5], Blo1[5]);
                    tf32_split(f3 * m1.y, Bhi1[6], Blo1[6]);
                    tf32_split(f3 * m1.z, Bhi1[7], Blo1[7]);
                    tf32_split(f3 * m1.w, Bhi1[8], Blo1[8]);
                    tf32_split(f3 * m2.x, Bhi1[9], Blo1[9]);
                }

                const uint4 Ah = sAhi[kq][chunk][lane];
                const uint4 Al = sAlo[kq][chunk][lane];
                #pragma unroll
                for (int c = 0; c < 10; ++c) {
                    MMA_TF32(C[c], Ah, Bhi0[c], Bhi1[c]);
                    MMA_TF32(C[c], Ah, Blo0[c], Blo1[c]);
                    MMA_TF32(C[c], Al, Bhi0[c], Bhi1[c]);
                }
            }

            // ---- compose this k-quarter's fragments into T-jet partials ----
            #pragma unroll
            for (int e = 0; e < 4; ++e) {
                const int k = kq * 16 + gid + ((e & 2) ? 8 : 0);
                float z[10];
                #pragma unroll
                for (int c = 0; c < 10; ++c) z[c] = C[c][e];
                z[0] += sB2[k];
                compose_scalar(z, sW3[k], &Tj[(e & 1) * 9]);
            }
        }

        // ---- reduce T-jet over the 8 lanes sharing each point-column ----
        #pragma unroll
        for (int q = 0; q < 18; ++q) {
            float v = Tj[q];
            v += __shfl_xor_sync(0xffffffffu, v, 4);
            v += __shfl_xor_sync(0xffffffffu, v, 8);
            v += __shfl_xor_sync(0xffffffffu, v, 16);
            Tj[q] = v;
        }

        // ---- epilogue: lanes 0..7 each finish one point ----
        if (lane < 8) {
            const int m   = lane & 3;
            const int sel = lane >> 2;
            const int pc  = 2 * m + sel;      // column within warp tile
            const int i   = base + pc;
            if (i < n) {
                const float* T = &Tj[sel * 9];
                const float Tp = T[0], Tt = T[1];
                const float Tpp = T[2], Tpt = T[3], Ttt = T[4];
                const float Tppp = T[5], Tppt = T[6], Tptt = T[7], Tttt = T[8];

                const float th = theta[i];
                float s, cn;
                sincosf(th, &s, &cn);
                const float r    = radius[i];
                const float invs = 1.0f / s;
                const float invr = 1.0f / r;

                const float ut = fmaf(Tp, invs, Tt);
                const float up = fmaf(Tp, invs, -Tt);

                const float u_th_t = -(Tpt + cn * Tt + s * Ttt);
                const float u_ph_p = fmaf(Tpp, invs, -Tpt);
                const float div = (u_th_t + u_ph_p) * invs * invr;

                const float c2s2 = cn * cn - s * s;
                const float u_th_tt = -(cn * Tpt + s * Tptt + 3.0f * s * cn * Ttt
                                        + c2s2 * Tt + s * s * Tttt);
                const float u_th_pp = -(fmaf(Tppp, invs, Tppt));
                const float u_ph_tt = cn * Tpt + s * Tptt - c2s2 * Tt
                                      - 3.0f * s * cn * Ttt - s * s * Tttt;
                const float u_ph_pp = fmaf(Tppp, invs, -Tppt);

                const float invr2  = invr * invr;
                const float invrs2 = invs * invs * invr2;
                const float lapt = fmaf(s * invr2, u_th_tt, u_th_pp * invrs2);
                const float lapp = fmaf(s * invr2, u_ph_tt, u_ph_pp * invrs2);
                const float comp = s * (lapt * lapt + lapp * lapp);
                const float sv   = -(ut * hth[i] + up * hph[i]) - brr[i] * div;
                const float tg   = div - ut * (s / cn) * invr;

                out[i]         = ut;
                out[n + i]     = up;
                out[2 * n + i] = div;
                out[3 * n + i] = sv;
                out[4 * n + i] = tg;
                out[5 * n + i] = comp;
            }
        }
    }
}

extern "C" void kernel_launch(void* const* d_in, const int* in_sizes, int n_in,
                              void* d_out, int out_size) {
    const float* phi    = (const float*)d_in[0];
    const float* theta  = (const float*)d_in[1];
    const float* radius = (const float*)d_in[2];
    const float* hth    = (const float*)d_in[3];
    const float* hph    = (const float*)d_in[4];
    const float* brr    = (const float*)d_in[5];
    const float* W1     = (const float*)d_in[6];
    const float* b1     = (const float*)d_in[7];
    const float* W2     = (const float*)d_in[8];
    const float* b2     = (const float*)d_in[9];
    const float* W3     = (const float*)d_in[10];
    const float* b3     = (const float*)d_in[11];
    float* out = (float*)d_out;
    const int n = in_sizes[0];

    pinn_flow_kernel<<<GRID_BLOCKS, THREADS>>>(
        phi, theta, radius, hth, hph, brr,
        W1, b1, W2, b2, W3, b3, out, n);
}